// round 14
// baseline (speedup 1.0000x reference)
#include <cuda_runtime.h>
#include <cstdint>
#include <cstddef>

typedef unsigned long long ULL;

// ---------- f32x2 packed-FMA helpers (sm_100+ only; 2x FFMA throughput) ----------
__device__ __forceinline__ ULL pack2f(float x) {
    unsigned r = __float_as_uint(x);
    ULL d;
    asm("mov.b64 %0, {%1, %1};" : "=l"(d) : "r"(r));
    return d;
}
__device__ __forceinline__ void fma2(ULL& d, ULL a, ULL b) {
    asm("fma.rn.f32x2 %0, %1, %2, %0;" : "+l"(d) : "l"(a), "l"(b));
}
__device__ __forceinline__ float2 un2(ULL v) {
    unsigned lo, hi;
    asm("mov.b64 {%0, %1}, %2;" : "=r"(lo), "=r"(hi) : "l"(v));
    return make_float2(__uint_as_float(lo), __uint_as_float(hi));
}

// ---------- problem constants ----------
static constexpr int Bb = 8;
static constexpr int Tt = 512;
static constexpr int Ff = 1024;
static constexpr int G4F = 4096;     // 4*F
static constexpr int Vv = 32000;
static constexpr int Mrows = Bb * Tt;  // 4096

// ---------- device scratch (allocation-free rule: static __device__ arrays) ----------
__device__ float g_xW[(size_t)Mrows * G4F];   // 64 MB: precomputed x@Wx + b
__device__ float g_hs[(size_t)Mrows * Ff];    // 16 MB: all hidden states
__device__ float g_h[2][Bb * Ff];             // ping-pong h state
__device__ float g_c[Bb * Ff];                // cell state

// ---------------------------------------------------------------------------
// Zero the recurrent state (must run at the START of every kernel_launch so
// graph replays are deterministic).
// ---------------------------------------------------------------------------
__global__ void init_state_kernel() {
    int i = blockIdx.x * blockDim.x + threadIdx.x;
    if (i < 2 * Bb * Ff) ((float*)g_h)[i] = 0.0f;
    if (i < Bb * Ff) g_c[i] = 0.0f;
}

// ---------------------------------------------------------------------------
// Tiled SGEMM: C[M,N] = A[M,K] @ B[K,N] + bias[N]
// Optional row gather on A (gidx != nullptr): A row m is A[gidx[m]].
// BM=BN=128, BK=16, 256 threads, 8x8 per thread with f32x2 packed FMA.
// Requires M%128==0, N%128==0, K%16==0 (holds for all our shapes).
// ---------------------------------------------------------------------------
__global__ __launch_bounds__(256, 2) void gemm_kernel(
    const float* __restrict__ A, const float* __restrict__ B,
    const float* __restrict__ bias, float* __restrict__ C,
    const int* __restrict__ gidx, int M, int N, int K)
{
    constexpr int BM = 128, BN = 128, BK = 16;
    __shared__ float As[BK][BM + 4];   // A tile transposed [k][m], padded
    __shared__ float Bs[BK][BN];       // B tile [k][n]

    const int tid = threadIdx.x;
    const int mBase = blockIdx.y * BM;
    const int nBase = blockIdx.x * BN;
    const int tr = tid >> 4;           // 0..15
    const int tc = tid & 15;           // 0..15
    const int m0 = tr * 8;
    const int n0 = tc * 8;

    ULL acc[8][4];
#pragma unroll
    for (int i = 0; i < 8; i++)
#pragma unroll
        for (int j = 0; j < 4; j++) acc[i][j] = 0ULL;

    const int la_r = tid >> 2;         // 0..63 (A tile row, +64 second pass)
    const int la_k = (tid & 3) * 4;    // 0,4,8,12
    const int lb_k = tid >> 5;         // 0..7 (B tile row, +8 second pass)
    const int lb_n = (tid & 31) * 4;

    for (int kt = 0; kt < K; kt += BK) {
        // ---- load A tile (gathered), store transposed ----
#pragma unroll
        for (int p = 0; p < 2; p++) {
            int r = la_r + p * 64;
            int grow = mBase + r;
            int arow = gidx ? gidx[grow] : grow;
            float4 v = *reinterpret_cast<const float4*>(
                &A[(size_t)arow * K + kt + la_k]);
            As[la_k + 0][r] = v.x;
            As[la_k + 1][r] = v.y;
            As[la_k + 2][r] = v.z;
            As[la_k + 3][r] = v.w;
        }
        // ---- load B tile ----
#pragma unroll
        for (int p = 0; p < 2; p++) {
            int kk = lb_k + p * 8;
            float4 v = *reinterpret_cast<const float4*>(
                &B[(size_t)(kt + kk) * N + nBase + lb_n]);
            *reinterpret_cast<float4*>(&Bs[kk][lb_n]) = v;
        }
        __syncthreads();

#pragma unroll
        for (int kk = 0; kk < BK; kk++) {
            float4 a0 = *reinterpret_cast<const float4*>(&As[kk][m0]);
            float4 a1 = *reinterpret_cast<const float4*>(&As[kk][m0 + 4]);
            ULL ad[8];
            ad[0] = pack2f(a0.x); ad[1] = pack2f(a0.y);
            ad[2] = pack2f(a0.z); ad[3] = pack2f(a0.w);
            ad[4] = pack2f(a1.x); ad[5] = pack2f(a1.y);
            ad[6] = pack2f(a1.z); ad[7] = pack2f(a1.w);
            ulonglong2 b0 = *reinterpret_cast<const ulonglong2*>(&Bs[kk][n0]);
            ulonglong2 b1 = *reinterpret_cast<const ulonglong2*>(&Bs[kk][n0 + 4]);
            ULL bb[4] = {b0.x, b0.y, b1.x, b1.y};
#pragma unroll
            for (int i = 0; i < 8; i++)
#pragma unroll
                for (int j = 0; j < 4; j++)
                    fma2(acc[i][j], ad[i], bb[j]);
        }
        __syncthreads();
    }

    // ---- epilogue: add bias, write ----
#pragma unroll
    for (int i = 0; i < 8; i++) {
        float out[8];
#pragma unroll
        for (int j = 0; j < 4; j++) {
            float2 f = un2(acc[i][j]);
            out[j * 2] = f.x;
            out[j * 2 + 1] = f.y;
        }
#pragma unroll
        for (int j = 0; j < 8; j++) out[j] += bias[nBase + n0 + j];
        float* cp = &C[(size_t)(mBase + m0 + i) * N + nBase + n0];
        *reinterpret_cast<float4*>(cp) = make_float4(out[0], out[1], out[2], out[3]);
        *reinterpret_cast<float4*>(cp + 4) = make_float4(out[4], out[5], out[6], out[7]);
    }
}

// ---------------------------------------------------------------------------
// One LSTM timestep. grid = 128 blocks x 256 threads.
// Block bl owns features [bl*8, bl*8+8): computes the 4 gate columns of
// z = xW[:,t,:] + h @ Wh for those features, then the pointwise update.
// h is ping-pong buffered (read t&1, write (t+1)&1) to avoid intra-step races.
// ---------------------------------------------------------------------------
__global__ __launch_bounds__(256) void lstm_step_kernel(
    const float* __restrict__ Wh, int t)
{
    __shared__ float sh_h[Bb][Ff + 4];       // padded rows: conflict-free LDS
    __shared__ float4 sh_part[4][Bb][8];     // [ks][batch][colquad] partials

    const int tid = threadIdx.x;
    const int f0 = blockIdx.x * 8;
    const float* __restrict__ hin = g_h[t & 1];

    // cooperative load of h[8][1024] into SMEM (float4)
#pragma unroll
    for (int p = 0; p < 8; p++) {
        int idx = tid + p * 256;     // float4 index 0..2047
        int b = idx >> 8;            // 256 float4 per batch row
        int c4 = idx & 255;
        float4 v = *reinterpret_cast<const float4*>(&hin[b * Ff + c4 * 4]);
        *reinterpret_cast<float4*>(&sh_h[b][c4 * 4]) = v;
    }
    __syncthreads();

    // thread -> (colquad cq 0..7, batch b 0..7, kslice ks 0..3)
    const int cq = tid & 7;
    const int b = (tid >> 3) & 7;
    const int ks = tid >> 6;
    // 8 colquads: gate g = cq>>1, quad q = cq&1 -> cols g*1024 + f0 + q*4 ..+3
    const int gcol = (cq >> 1) * Ff + f0 + (cq & 1) * 4;

    ULL acc0 = 0ULL, acc1 = 0ULL;
    const int kbeg = ks * 256;
#pragma unroll 4
    for (int k = kbeg; k < kbeg + 256; k++) {
        ulonglong2 w = *reinterpret_cast<const ulonglong2*>(
            &Wh[(size_t)k * G4F + gcol]);
        ULL hd = pack2f(sh_h[b][k]);
        fma2(acc0, hd, w.x);
        fma2(acc1, hd, w.y);
    }
    {
        float2 p0 = un2(acc0);
        float2 p1 = un2(acc1);
        sh_part[ks][b][cq] = make_float4(p0.x, p0.y, p1.x, p1.y);
    }
    __syncthreads();

    // reduction over kslices + pointwise LSTM update (64 threads)
    if (tid < 64) {
        int b2 = tid >> 3;
        int f = tid & 7;
        float z[4];
#pragma unroll
        for (int g = 0; g < 4; g++) {
            int cqq = g * 2 + (f >> 2);
            int comp = f & 3;
            float s = 0.0f;
#pragma unroll
            for (int kss = 0; kss < 4; kss++) {
                const float* p = reinterpret_cast<const float*>(&sh_part[kss][b2][cqq]);
                s += p[comp];
            }
            s += g_xW[((size_t)(b2 * Tt + t)) * G4F + g * Ff + f0 + f];
            z[g] = s;
        }
        int fi = b2 * Ff + f0 + f;
        float c_old = g_c[fi];
        float ig = 1.0f / (1.0f + expf(-z[0]));
        float fg = 1.0f / (1.0f + expf(-z[1]));
        float gg = tanhf(z[2]);
        float og = 1.0f / (1.0f + expf(-z[3]));
        float c_new = fg * c_old + ig * gg;
        float h_new = og * tanhf(c_new);
        g_c[fi] = c_new;
        g_h[(t + 1) & 1][fi] = h_new;
        g_hs[((size_t)(b2 * Tt + t)) * Ff + f0 + f] = h_new;
    }
}

// ---------------------------------------------------------------------------
extern "C" void kernel_launch(void* const* d_in, const int* in_sizes, int n_in,
                              void* d_out, int out_size)
{
    (void)in_sizes; (void)n_in; (void)out_size;
    const int*   tokens = (const int*)d_in[0];
    const float* embed  = (const float*)d_in[1];
    const float* Wx     = (const float*)d_in[2];
    const float* Wh     = (const float*)d_in[3];
    const float* bvec   = (const float*)d_in[4];
    const float* Wd     = (const float*)d_in[5];
    const float* bd     = (const float*)d_in[6];
    float* out = (float*)d_out;

    void *xw_p = nullptr, *hs_p = nullptr;
    cudaGetSymbolAddress(&xw_p, g_xW);
    cudaGetSymbolAddress(&hs_p, g_hs);
    float* xW = (float*)xw_p;
    float* hs = (float*)hs_p;

    // 1) reset recurrent state (deterministic across graph replays)
    init_state_kernel<<<64, 256>>>();

    // 2) xW = embed[tokens] @ Wx + b   (gathered A rows)
    {
        dim3 grid(G4F / 128, Mrows / 128);   // (32, 32)
        gemm_kernel<<<grid, 256>>>(embed, Wx, bvec, xW, tokens,
                                   Mrows, G4F, Ff);
    }

    // 3) 512 sequential LSTM steps
    for (int t = 0; t < Tt; t++) {
        lstm_step_kernel<<<128, 256>>>(Wh, t);
    }

    // 4) logits = hs @ Wd + bd
    {
        dim3 grid(Vv / 128, Mrows / 128);    // (250, 32)
        gemm_kernel<<<grid, 256>>>(hs, Wd, bd, out, nullptr,
                                   Mrows, Vv, Ff);
    }
}

// round 15
// speedup vs baseline: 1.8660x; 1.8660x over previous
#include <cuda_runtime.h>
#include <cstdint>
#include <cstddef>

typedef unsigned long long ULL;

// ---------- f32x2 packed-FMA helpers (sm_100+ only; 2x FFMA throughput) ----------
__device__ __forceinline__ ULL pack2f(float x) {
    unsigned r = __float_as_uint(x);
    ULL d;
    asm("mov.b64 %0, {%1, %1};" : "=l"(d) : "r"(r));
    return d;
}
__device__ __forceinline__ void fma2(ULL& d, ULL a, ULL b) {
    asm("fma.rn.f32x2 %0, %1, %2, %0;" : "+l"(d) : "l"(a), "l"(b));
}
__device__ __forceinline__ void add2(ULL& d, ULL a) {
    asm("add.rn.f32x2 %0, %0, %1;" : "+l"(d) : "l"(a));
}
__device__ __forceinline__ float2 un2(ULL v) {
    unsigned lo, hi;
    asm("mov.b64 {%0, %1}, %2;" : "=r"(lo), "=r"(hi) : "l"(v));
    return make_float2(__uint_as_float(lo), __uint_as_float(hi));
}
__device__ __forceinline__ ULL packpair(float x, float y) {
    ULL d;
    asm("mov.b64 %0, {%1, %2};" : "=l"(d)
        : "r"(__float_as_uint(x)), "r"(__float_as_uint(y)));
    return d;
}

// ---------- problem constants ----------
static constexpr int Bb = 8;
static constexpr int Tt = 512;
static constexpr int Ff = 1024;
static constexpr int G4F = 4096;     // 4*F
static constexpr int Vv = 32000;
static constexpr int Mrows = Bb * Tt;  // 4096

static constexpr int NBLK = 128;     // LSTM persistent CTAs (1/SM, single wave)

// ---------- device scratch (allocation-free rule: static __device__ arrays) ----------
__device__ float g_xW[(size_t)Mrows * G4F];   // 64 MB: precomputed x@Wx + b
__device__ float g_hs[(size_t)Mrows * Ff];    // 16 MB: all hidden states
__device__ float g_h[2][Bb * Ff];             // ping-pong h state
__device__ unsigned g_bar_cnt;                // grid barrier counter

// ---------------------------------------------------------------------------
// Reset recurrent state + barrier (start of every kernel_launch -> graph-
// replay deterministic).
// ---------------------------------------------------------------------------
__global__ void init_state_kernel() {
    int i = blockIdx.x * blockDim.x + threadIdx.x;
    if (i == 0) g_bar_cnt = 0;
    if (i < 2 * Bb * Ff) ((float*)g_h)[i] = 0.0f;
}

// ---------------------------------------------------------------------------
// Tiled SGEMM: C[M,N] = A[M,K] @ B[K,N] + bias[N]
// Optional row gather on A (gidx != nullptr): A row m is A[gidx[m]].
// BM=BN=128, BK=16, 256 threads, 8x8 per thread with f32x2 packed FMA.
// ---------------------------------------------------------------------------
__global__ __launch_bounds__(256, 2) void gemm_kernel(
    const float* __restrict__ A, const float* __restrict__ B,
    const float* __restrict__ bias, float* __restrict__ C,
    const int* __restrict__ gidx, int M, int N, int K)
{
    constexpr int BM = 128, BN = 128, BK = 16;
    __shared__ float As[BK][BM + 4];   // A tile transposed [k][m], padded
    __shared__ float Bs[BK][BN];       // B tile [k][n]

    const int tid = threadIdx.x;
    const int mBase = blockIdx.y * BM;
    const int nBase = blockIdx.x * BN;
    const int tr = tid >> 4;           // 0..15
    const int tc = tid & 15;           // 0..15
    const int m0 = tr * 8;
    const int n0 = tc * 8;

    ULL acc[8][4];
#pragma unroll
    for (int i = 0; i < 8; i++)
#pragma unroll
        for (int j = 0; j < 4; j++) acc[i][j] = 0ULL;

    const int la_r = tid >> 2;         // 0..63 (A tile row, +64 second pass)
    const int la_k = (tid & 3) * 4;    // 0,4,8,12
    const int lb_k = tid >> 5;         // 0..7 (B tile row, +8 second pass)
    const int lb_n = (tid & 31) * 4;

    for (int kt = 0; kt < K; kt += BK) {
        // ---- load A tile (gathered), store transposed ----
#pragma unroll
        for (int p = 0; p < 2; p++) {
            int r = la_r + p * 64;
            int grow = mBase + r;
            int arow = gidx ? gidx[grow] : grow;
            float4 v = *reinterpret_cast<const float4*>(
                &A[(size_t)arow * K + kt + la_k]);
            As[la_k + 0][r] = v.x;
            As[la_k + 1][r] = v.y;
            As[la_k + 2][r] = v.z;
            As[la_k + 3][r] = v.w;
        }
        // ---- load B tile ----
#pragma unroll
        for (int p = 0; p < 2; p++) {
            int kk = lb_k + p * 8;
            float4 v = *reinterpret_cast<const float4*>(
                &B[(size_t)(kt + kk) * N + nBase + lb_n]);
            *reinterpret_cast<float4*>(&Bs[kk][lb_n]) = v;
        }
        __syncthreads();

#pragma unroll
        for (int kk = 0; kk < BK; kk++) {
            float4 a0 = *reinterpret_cast<const float4*>(&As[kk][m0]);
            float4 a1 = *reinterpret_cast<const float4*>(&As[kk][m0 + 4]);
            ULL ad[8];
            ad[0] = pack2f(a0.x); ad[1] = pack2f(a0.y);
            ad[2] = pack2f(a0.z); ad[3] = pack2f(a0.w);
            ad[4] = pack2f(a1.x); ad[5] = pack2f(a1.y);
            ad[6] = pack2f(a1.z); ad[7] = pack2f(a1.w);
            ulonglong2 b0 = *reinterpret_cast<const ulonglong2*>(&Bs[kk][n0]);
            ulonglong2 b1 = *reinterpret_cast<const ulonglong2*>(&Bs[kk][n0 + 4]);
            ULL bb[4] = {b0.x, b0.y, b1.x, b1.y};
#pragma unroll
            for (int i = 0; i < 8; i++)
#pragma unroll
                for (int j = 0; j < 4; j++)
                    fma2(acc[i][j], ad[i], bb[j]);
        }
        __syncthreads();
    }

    // ---- epilogue: add bias, write ----
#pragma unroll
    for (int i = 0; i < 8; i++) {
        float out[8];
#pragma unroll
        for (int j = 0; j < 4; j++) {
            float2 f = un2(acc[i][j]);
            out[j * 2] = f.x;
            out[j * 2 + 1] = f.y;
        }
#pragma unroll
        for (int j = 0; j < 8; j++) out[j] += bias[nBase + n0 + j];
        float* cp = &C[(size_t)(mBase + m0 + i) * N + nBase + n0];
        *reinterpret_cast<float4*>(cp) = make_float4(out[0], out[1], out[2], out[3]);
        *reinterpret_cast<float4*>(cp + 4) = make_float4(out[4], out[5], out[6], out[7]);
    }
}

// ---------------------------------------------------------------------------
// Persistent LSTM kernel: 128 CTAs x 256 threads, ALL 512 timesteps in one
// launch. CTA bl owns features [bl*8, bl*8+8) -> 32 Wh columns (4 gates x 8),
// kept in SMEM for the whole kernel (loaded once). Cell state lives in SMEM.
// Steps are separated by a gpu-scope grid barrier (single wave: 128 CTAs,
// 198KB SMEM -> exactly 1 CTA/SM, 148 SMs, so co-residency is guaranteed).
//
// Per step:
//   1. cooperative load h[8][1024] (32KB) from ping-pong global buffer
//   2. matvec: thread (cpg=tid&7, ks=tid>>3) computes 2 packed cols x 8
//      batches over k-slice [ks*32, ks*32+32) with f32x2 FMAs
//   3. SMEM reduction over 32 k-slices
//   4. 64 threads do the gate pointwise, update SMEM c, write h ping-pong
//   5. grid barrier
// ---------------------------------------------------------------------------
struct LstmSmem {
    ULL   w[1024][16];   // 128 KB  Wh slice, cp-pair packed: w[k][cp]
    float h[8][1024];    //  32 KB  current h
    ULL   p[32][128];    //  32 KB  k-slice partials [ks][cp*8+b]
    ULL   zz[128];       //   1 KB  reduced z pairs
    float c[64];         // cell state (persists across steps)
};

__global__ __launch_bounds__(256, 1) void lstm_persistent_kernel(
    const float* __restrict__ Wh)
{
    extern __shared__ char smem_raw[];
    LstmSmem& S = *reinterpret_cast<LstmSmem*>(smem_raw);
    const int tid = threadIdx.x;
    const int f0 = blockIdx.x * 8;

    // ---- one-time: load this block's 32 Wh columns into SMEM ----
    // col(g, j) = g*1024 + f0 + j ;  cp = g*4 + j/2
    for (int idx = tid; idx < 1024 * 8; idx += 256) {
        int k = idx >> 3;
        int g = (idx >> 1) & 3;
        int half = idx & 1;
        float4 v = *reinterpret_cast<const float4*>(
            &Wh[(size_t)k * G4F + g * Ff + f0 + half * 4]);
        S.w[k][g * 4 + half * 2]     = packpair(v.x, v.y);
        S.w[k][g * 4 + half * 2 + 1] = packpair(v.z, v.w);
    }
    if (tid < 64) S.c[tid] = 0.0f;
    __syncthreads();

    const int cpg = tid & 7;    // column-pair group: cps {2*cpg, 2*cpg+1}
    const int ks  = tid >> 3;   // k-slice 0..31 (32 k each)
    const int kb  = ks * 32;

    unsigned* bar = &g_bar_cnt;

    for (int t = 0; t < Tt; t++) {
        const float* __restrict__ hin = g_h[t & 1];

        // ---- load h into SMEM (float4, fully coalesced) ----
#pragma unroll
        for (int pp = 0; pp < 8; pp++) {
            int idx = tid + pp * 256;    // float4 index 0..2047
            int b = idx >> 8;
            int c4 = idx & 255;
            *reinterpret_cast<float4*>(&S.h[b][c4 * 4]) =
                *reinterpret_cast<const float4*>(&hin[b * Ff + c4 * 4]);
        }

        // ---- prefetch xW for the pointwise stage (hides DRAM latency) ----
        float xwp[4] = {0.f, 0.f, 0.f, 0.f};
        if (tid < 64) {
            int b = tid >> 3, j = tid & 7;
#pragma unroll
            for (int g = 0; g < 4; g++)
                xwp[g] = __ldg(&g_xW[((size_t)(b * Tt + t)) * G4F + g * Ff + f0 + j]);
        }
        __syncthreads();

        // ---- matvec over this thread's k-slice ----
        ULL a0[8], a1[8];
#pragma unroll
        for (int b = 0; b < 8; b++) { a0[b] = 0ULL; a1[b] = 0ULL; }

        for (int i = 0; i < 32; i += 4) {
            float4 hv[8];
#pragma unroll
            for (int b = 0; b < 8; b++)
                hv[b] = *reinterpret_cast<const float4*>(&S.h[b][kb + i]);
            const float* hp = reinterpret_cast<const float*>(hv);
#pragma unroll
            for (int u = 0; u < 4; u++) {
                ulonglong2 w = *reinterpret_cast<const ulonglong2*>(
                    &S.w[kb + i + u][cpg * 2]);
#pragma unroll
                for (int b = 0; b < 8; b++) {
                    ULL hd = pack2f(hp[b * 4 + u]);
                    fma2(a0[b], hd, w.x);
                    fma2(a1[b], hd, w.y);
                }
            }
        }

        // ---- write partials ----
#pragma unroll
        for (int b = 0; b < 8; b++) {
            S.p[ks][(2 * cpg) * 8 + b]     = a0[b];
            S.p[ks][(2 * cpg + 1) * 8 + b] = a1[b];
        }
        __syncthreads();

        // ---- reduce 32 k-slices (128 threads, one combo each) ----
        if (tid < 128) {
            ULL s = S.p[0][tid];
#pragma unroll
            for (int q = 1; q < 32; q++) add2(s, S.p[q][tid]);
            S.zz[tid] = s;
        }
        __syncthreads();

        // ---- pointwise LSTM update (64 threads: batch b, feature j) ----
        if (tid < 64) {
            int b = tid >> 3, j = tid & 7;
            float z[4];
#pragma unroll
            for (int g = 0; g < 4; g++) {
                float2 f2 = un2(S.zz[(g * 4 + (j >> 1)) * 8 + b]);
                z[g] = ((j & 1) ? f2.y : f2.x) + xwp[g];
            }
            float c_old = S.c[tid];
            float ig = 1.0f / (1.0f + expf(-z[0]));
            float fg = 1.0f / (1.0f + expf(-z[1]));
            float gg = tanhf(z[2]);
            float og = 1.0f / (1.0f + expf(-z[3]));
            float c_new = fg * c_old + ig * gg;
            float h_new = og * tanhf(c_new);
            S.c[tid] = c_new;
            g_h[(t + 1) & 1][b * Ff + f0 + j] = h_new;
            g_hs[((size_t)(b * Tt + t)) * Ff + f0 + j] = h_new;
        }

        // ---- grid barrier (skip after last step; kernel end orders it) ----
        if (t < Tt - 1) {
            __syncthreads();
            if (tid == 0) {
                __threadfence();
                asm volatile("red.release.gpu.add.u32 [%0], 1;"
                             :: "l"(bar) : "memory");
                unsigned target = (unsigned)(t + 1) * (unsigned)NBLK;
                unsigned v;
                do {
                    asm volatile("ld.acquire.gpu.u32 %0, [%1];"
                                 : "=r"(v) : "l"(bar));
                } while (v < target);
            }
            __syncthreads();
        }
    }
}

// ---------------------------------------------------------------------------
extern "C" void kernel_launch(void* const* d_in, const int* in_sizes, int n_in,
                              void* d_out, int out_size)
{
    (void)in_sizes; (void)n_in; (void)out_size;
    const int*   tokens = (const int*)d_in[0];
    const float* embed  = (const float*)d_in[1];
    const float* Wx     = (const float*)d_in[2];
    const float* Wh     = (const float*)d_in[3];
    const float* bvec   = (const float*)d_in[4];
    const float* Wd     = (const float*)d_in[5];
    const float* bd     = (const float*)d_in[6];
    float* out = (float*)d_out;

    void *xw_p = nullptr, *hs_p = nullptr;
    cudaGetSymbolAddress(&xw_p, g_xW);
    cudaGetSymbolAddress(&hs_p, g_hs);
    float* xW = (float*)xw_p;
    float* hs = (float*)hs_p;

    // allow 198KB dynamic SMEM for the persistent kernel (idempotent)
    cudaFuncSetAttribute(lstm_persistent_kernel,
                         cudaFuncAttributeMaxDynamicSharedMemorySize,
                         (int)sizeof(LstmSmem));

    // 1) reset recurrent state + barrier counter
    init_state_kernel<<<64, 256>>>();

    // 2) xW = embed[tokens] @ Wx + b   (gathered A rows)
    {
        dim3 grid(G4F / 128, Mrows / 128);   // (32, 32)
        gemm_kernel<<<grid, 256>>>(embed, Wx, bvec, xW, tokens,
                                   Mrows, G4F, Ff);
    }

    // 3) all 512 LSTM steps in ONE persistent kernel
    lstm_persistent_kernel<<<NBLK, 256, sizeof(LstmSmem)>>>(Wh);

    // 4) logits = hs @ Wd + bd
    {
        dim3 grid(Vv / 128, Mrows / 128);    // (250, 32)
        gemm_kernel<<<grid, 256>>>(hs, Wd, bd, out, nullptr,
                                   Mrows, Vv, Ff);
    }
}